// round 3
// baseline (speedup 1.0000x reference)
#include <cuda_runtime.h>
#include <cuda_bf16.h>
#include <cstdint>

// ---------------- problem constants ----------------
#define NUM_CHARS 128
#define UNITS     256
#define BATCH     512
#define SEQ       1024

// ---------------- decomposition ----------------
#define GROUPS 16      // batch groups (= clusters)
#define CPG    8       // CTAs per group (cluster size)
#define MBATCH 32      // batch rows per group
#define UC     32      // units per CTA
#define KDIM   256     // h dimension (MMA K)
#define NCTAS  (GROUPS*CPG)
#define NTHREADS 128

// ---------------- smem layout (byte offsets) ----------------
#define OFF_TOK    0                        // 32 ints
#define OFF_AHI    1024                     // W_hi slice [128 m][256 k] bf16 swizzled = 64KB
#define OFF_ALO    (OFF_AHI + 65536)        // W_lo slice                              = 64KB
#define OFF_BHI    (OFF_ALO + 65536)        // h_hi tile [32 n][256 k] bf16 swizzled   = 16KB
#define OFF_BLO    (OFF_BHI + 16384)        // h_lo tile                               = 16KB
#define OFF_WX     (OFF_BLO + 16384)        // Wx slice fp32 [128 m][130 ch]           = 66560B
#define SMEM_TOTAL (OFF_WX + 66560)         // = 231424 <= 232448 (227KB cap)

// ---------------- global scratch ----------------
__device__ unsigned g_h[2][BATCH * UNITS];   // packed (bf16 hi | bf16 lo << 16), double-buffered

// ---------------- helpers ----------------
__device__ __forceinline__ uint32_t smem_u32(const void* p) {
    uint32_t a;
    asm("{ .reg .u64 t; cvta.to.shared.u64 t, %1; cvt.u32.u64 %0, t; }" : "=r"(a) : "l"(p));
    return a;
}
#define CLUSTER_SYNC() do { \
    asm volatile("barrier.cluster.arrive.aligned;" ::: "memory"); \
    asm volatile("barrier.cluster.wait.aligned;" ::: "memory"); } while (0)

// row-major tile, 512B row stride, 16B chunks XOR-swizzled by row%8 (conflict-free ldmatrix)
__device__ __forceinline__ uint32_t swz(int row, int k) {
    return (uint32_t)row * 512u
         + (((((uint32_t)k >> 3) << 4)) ^ (((uint32_t)row & 7u) << 4))
         + (((uint32_t)k & 7u) << 1);
}

__device__ __forceinline__ void ldsm_x4(uint32_t r[4], uint32_t addr) {
    asm volatile("ldmatrix.sync.aligned.m8n8.x4.shared.b16 {%0,%1,%2,%3}, [%4];"
                 : "=r"(r[0]), "=r"(r[1]), "=r"(r[2]), "=r"(r[3]) : "r"(addr));
}

__device__ __forceinline__ void mma_bf16(float c[4],
                                         uint32_t a0, uint32_t a1, uint32_t a2, uint32_t a3,
                                         uint32_t b0, uint32_t b1) {
    asm volatile("mma.sync.aligned.m16n8k16.row.col.f32.bf16.bf16.f32 "
                 "{%0,%1,%2,%3}, {%4,%5,%6,%7}, {%8,%9}, {%0,%1,%2,%3};"
                 : "+f"(c[0]), "+f"(c[1]), "+f"(c[2]), "+f"(c[3])
                 : "r"(a0), "r"(a1), "r"(a2), "r"(a3), "r"(b0), "r"(b1));
}

__device__ __forceinline__ float sigm(float x) { return 1.0f / (1.0f + __expf(-x)); }
__device__ __forceinline__ float tanh_fast(float x) { float e = __expf(2.0f * x); return 1.0f - 2.0f / (e + 1.0f); }

// ---------------- init kernel: zero g_h[0] ----------------
__global__ void init_kernel() {
    int i = blockIdx.x * blockDim.x + threadIdx.x;
    for (; i < BATCH * UNITS; i += gridDim.x * blockDim.x) g_h[0][i] = 0u;
}

// ---------------- main persistent kernel ----------------
__global__ void __launch_bounds__(NTHREADS, 1) __cluster_dims__(CPG, 1, 1)
lstm_kernel(const int* __restrict__ tokens,
            const float* __restrict__ Wx,
            const float* __restrict__ Wh,
            const float* __restrict__ bias,
            const float* __restrict__ Wd,
            const float* __restrict__ bd,
            float* __restrict__ out) {
    extern __shared__ __align__(1024) char smem[];
    const uint32_t sb = smem_u32(smem);
    const int tid = threadIdx.x;
    const int w   = tid >> 5;            // warp index
    const int L   = tid & 31;
    const int group = blockIdx.x >> 3;
    const int r     = blockIdx.x & 7;    // cluster rank
    const int gbase = group * MBATCH;

    float* wx_s  = (float*)(smem + OFF_WX);
    int*   tok_s = (int*)(smem + OFF_TOK);

    // ---- prologue ----
    // A-row mapping (per warp block of 32 rows rw): gate = rw>>3 (i,j,f,o), unit_local = w*8 + (rw&7).
    // This puts all 4 gates of unit w*8+(L>>2) in one lane's MMA accumulator fragments.
    {
        const int m = tid;                        // 0..127 A-row within CTA
        const int rw = m & 31;
        const int gate = rw >> 3;
        const int ulocal = (m >> 5) * 8 + (rw & 7);
        const int col = gate * 256 + r * UC + ulocal;   // global gate column in [0,1024)
        for (int k = 0; k < KDIM; k++) {
            float wv = Wh[k * 1024 + col];
            __nv_bfloat16 hi = __float2bfloat16(wv);
            float rem = wv - __bfloat162float(hi);
            __nv_bfloat16 lo = __float2bfloat16(rem);
            uint32_t s = swz(m, k);
            *(__nv_bfloat16*)(smem + OFF_AHI + s) = hi;
            *(__nv_bfloat16*)(smem + OFF_ALO + s) = lo;
        }
        // Wx fp32 slice: row (gate*32 + ulocal), stride 130 floats
        for (int ch = 0; ch < NUM_CHARS; ch++)
            wx_s[(gate * 32 + ulocal) * 130 + ch] = Wx[ch * 1024 + col];
    }

    // per-lane owned unit + bias registers
    const int ul = w * 8 + (L >> 2);             // unit local 0..31
    const float bi = bias[0 * 256 + r * UC + ul];
    const float bj = bias[1 * 256 + r * UC + ul];
    const float bf = bias[2 * 256 + r * UC + ul];
    const float bo = bias[3 * 256 + r * UC + ul];
    const float* wxi = &wx_s[(0 * 32 + ul) * 130];
    const float* wxj = &wx_s[(1 * 32 + ul) * 130];
    const float* wxf = &wx_s[(2 * 32 + ul) * 130];
    const float* wxo = &wx_s[(3 * 32 + ul) * 130];

    // ---- per-lane ldmatrix address components ----
    const int rA   = (L & 7) + 8 * ((L >> 3) & 1);
    const uint32_t koffA = (L >> 4) ? 16u : 0u;
    const int rowA0 = w * 32 + rA;
    const int rowA1 = rowA0 + 16;
    const uint32_t xA = ((uint32_t)rowA0 & 7u) << 4;
    const uint32_t aHi0 = sb + OFF_AHI + rowA0 * 512u;
    const uint32_t aHi1 = sb + OFF_AHI + rowA1 * 512u;
    const uint32_t aLo0 = sb + OFF_ALO + rowA0 * 512u;
    const uint32_t aLo1 = sb + OFF_ALO + rowA1 * 512u;
    const int rB = L & 7;
    const uint32_t koffB = ((L >> 3) & 1) ? 16u : 0u;
    const int nB0 = ((L >> 4) & 1) * 8 + rB;
    const int nB1 = nB0 + 16;
    const uint32_t xB = ((uint32_t)rB & 7u) << 4;
    const uint32_t bHi0 = sb + OFF_BHI + nB0 * 512u;
    const uint32_t bHi1 = sb + OFF_BHI + nB1 * 512u;
    const uint32_t bLo0 = sb + OFF_BLO + nB0 * 512u;
    const uint32_t bLo1 = sb + OFF_BLO + nB1 * 512u;

    float c_reg[8];
#pragma unroll
    for (int k = 0; k < 8; k++) c_reg[k] = 0.0f;

    CLUSTER_SYNC();   // prologue done cluster-wide

    // ---- 1024 recurrent steps ----
    for (int t = 0; t < SEQ; t++) {
        // load h tiles (packed bf16 hi/lo), unpack into swizzled Bhi/Blo
        {
            const uint4* src = (const uint4*)&g_h[t & 1][gbase * UNITS];
#pragma unroll
            for (int ii = 0; ii < 16; ii++) {
                int idx4 = tid + (ii << 7);
                uint4 p = __ldcg(src + idx4);
                int n  = idx4 >> 6;
                int k4 = (idx4 & 63) << 2;
                uint32_t hi01 = (p.x & 0xFFFFu) | (p.y << 16);
                uint32_t hi23 = (p.z & 0xFFFFu) | (p.w << 16);
                uint32_t lo01 = (p.x >> 16) | (p.y & 0xFFFF0000u);
                uint32_t lo23 = (p.z >> 16) | (p.w & 0xFFFF0000u);
                uint32_t s = swz(n, k4);
                *(uint2*)(smem + OFF_BHI + s) = make_uint2(hi01, hi23);
                *(uint2*)(smem + OFF_BLO + s) = make_uint2(lo01, lo23);
            }
        }
        if (tid < MBATCH) tok_s[tid] = tokens[(gbase + tid) * SEQ + t];
        __syncthreads();

        // ---- MMA: gates[128,32] = Whi*hhi + Whi*hlo + Wlo*hhi over K=256 ----
        float acc[2][4][4];
#pragma unroll
        for (int mt = 0; mt < 2; mt++)
#pragma unroll
            for (int nb = 0; nb < 4; nb++)
#pragma unroll
                for (int e = 0; e < 4; e++) acc[mt][nb][e] = 0.0f;

#pragma unroll 4
        for (int ks = 0; ks < 16; ks++) {
            const uint32_t ka = ((uint32_t)(ks * 32) + koffA) ^ xA;
            const uint32_t kb = ((uint32_t)(ks * 32) + koffB) ^ xB;
            uint32_t Ah0[4], Ah1[4], Al0[4], Al1[4];
            uint32_t Bh0[4], Bh1[4], Bl0[4], Bl1[4];
            ldsm_x4(Ah0, aHi0 + ka);
            ldsm_x4(Ah1, aHi1 + ka);
            ldsm_x4(Al0, aLo0 + ka);
            ldsm_x4(Al1, aLo1 + ka);
            ldsm_x4(Bh0, bHi0 + kb);
            ldsm_x4(Bh1, bHi1 + kb);
            ldsm_x4(Bl0, bLo0 + kb);
            ldsm_x4(Bl1, bLo1 + kb);
            uint32_t* Bh[4] = { &Bh0[0], &Bh0[2], &Bh1[0], &Bh1[2] };
            uint32_t* Bl[4] = { &Bl0[0], &Bl0[2], &Bl1[0], &Bl1[2] };
#pragma unroll
            for (int nb = 0; nb < 4; nb++) {
                mma_bf16(acc[0][nb], Ah0[0], Ah0[1], Ah0[2], Ah0[3], Bh[nb][0], Bh[nb][1]);
                mma_bf16(acc[1][nb], Ah1[0], Ah1[1], Ah1[2], Ah1[3], Bh[nb][0], Bh[nb][1]);
                mma_bf16(acc[0][nb], Ah0[0], Ah0[1], Ah0[2], Ah0[3], Bl[nb][0], Bl[nb][1]);
                mma_bf16(acc[1][nb], Ah1[0], Ah1[1], Ah1[2], Ah1[3], Bl[nb][0], Bl[nb][1]);
                mma_bf16(acc[0][nb], Al0[0], Al0[1], Al0[2], Al0[3], Bh[nb][0], Bh[nb][1]);
                mma_bf16(acc[1][nb], Al1[0], Al1[1], Al1[2], Al1[3], Bh[nb][0], Bh[nb][1]);
            }
        }

        // ---- LSTM elementwise: fully in registers (lane owns unit ul, 8 batch cols) ----
        // acc[0][nb][j]   = gate_i (rows 0-7 of tile0)     acc[0][nb][2+j] = gate_j (rows 8-15)
        // acc[1][nb][j]   = gate_f (rows 0-7 of tile1)     acc[1][nb][2+j] = gate_o (rows 8-15)
        {
            unsigned* dst = &g_h[(t + 1) & 1][0];
#pragma unroll
            for (int nb = 0; nb < 4; nb++) {
#pragma unroll
                for (int j = 0; j < 2; j++) {
                    const int bb = nb * 8 + (L & 3) * 2 + j;
                    const int tok = tok_s[bb];
                    float gi = acc[0][nb][j]     + wxi[tok] + bi;
                    float gj = acc[0][nb][2 + j] + wxj[tok] + bj;
                    float gf = acc[1][nb][j]     + wxf[tok] + bf;
                    float go = acc[1][nb][2 + j] + wxo[tok] + bo;
                    float nc = c_reg[nb * 2 + j] * sigm(gf + 1.0f) + sigm(gi) * tanh_fast(gj);
                    c_reg[nb * 2 + j] = nc;
                    float nh = tanh_fast(nc) * sigm(go);
                    __nv_bfloat16 hi = __float2bfloat16(nh);
                    float rem = nh - __bfloat162float(hi);
                    __nv_bfloat16 lo = __float2bfloat16(rem);
                    unsigned packed = (unsigned)__bfloat16_as_ushort(hi) | ((unsigned)__bfloat16_as_ushort(lo) << 16);
                    __stcg(&dst[(gbase + bb) * UNITS + r * UC + ul], packed);
                }
            }
        }
        // cluster-wide barrier: release/acquire orders the L2 h stores for peer CTAs
        CLUSTER_SYNC();
    }

    // ---- dense head: logits = h @ W_dense + b_dense (final h in g_h[0]) ----
    {
        float* hs = (float*)(smem + OFF_AHI);   // reuse A region: 4 rows x 256 fp32
        const int bstart = r * 4;
        for (int i = tid; i < 4 * UNITS; i += NTHREADS) {
            unsigned p = __ldcg(&g_h[0][(gbase + bstart + (i >> 8)) * UNITS + (i & 255)]);
            hs[i] = __bfloat162float(__ushort_as_bfloat16((unsigned short)(p & 0xFFFFu))) +
                    __bfloat162float(__ushort_as_bfloat16((unsigned short)(p >> 16)));
        }
        __syncthreads();
        const int n = tid;  // 128 threads = 128 output chars
        float a0 = bd[n], a1 = bd[n], a2 = bd[n], a3 = bd[n];
        for (int k = 0; k < UNITS; k++) {
            float wv = Wd[k * NUM_CHARS + n];
            a0 += hs[k] * wv;
            a1 += hs[256 + k] * wv;
            a2 += hs[512 + k] * wv;
            a3 += hs[768 + k] * wv;
        }
        out[(gbase + bstart + 0) * NUM_CHARS + n] = a0;
        out[(gbase + bstart + 1) * NUM_CHARS + n] = a1;
        out[(gbase + bstart + 2) * NUM_CHARS + n] = a2;
        out[(gbase + bstart + 3) * NUM_CHARS + n] = a3;
    }
    CLUSTER_SYNC();
}

// ---------------- host launcher ----------------
extern "C" void kernel_launch(void* const* d_in, const int* in_sizes, int n_in,
                              void* d_out, int out_size) {
    (void)in_sizes; (void)n_in; (void)out_size;
    const int*   tokens = (const int*)d_in[0];
    const float* Wx     = (const float*)d_in[1];
    const float* Wh     = (const float*)d_in[2];
    const float* b      = (const float*)d_in[3];
    const float* Wd     = (const float*)d_in[4];
    const float* bdn    = (const float*)d_in[5];
    float* out = (float*)d_out;

    cudaFuncSetAttribute(lstm_kernel, cudaFuncAttributeMaxDynamicSharedMemorySize, SMEM_TOTAL);

    init_kernel<<<128, 256>>>();
    lstm_kernel<<<NCTAS, NTHREADS, SMEM_TOTAL>>>(tokens, Wx, Wh, b, Wd, bdn, out);
}

// round 7
// speedup vs baseline: 1.3197x; 1.3197x over previous
#include <cuda_runtime.h>
#include <cuda_bf16.h>
#include <cstdint>

// ---------------- problem constants ----------------
#define NUM_CHARS 128
#define UNITS     256
#define BATCH     512
#define SEQ       1024

// ---------------- decomposition ----------------
#define GROUPS 16      // batch groups (= clusters)
#define CPG    8       // CTAs per group (cluster size)
#define MBATCH 32      // batch rows per group
#define UC     32      // units per CTA
#define KDIM   256     // h dimension (MMA K)
#define NCTAS  (GROUPS*CPG)
#define NTHREADS 256   // 8 warps: 4 m-groups x 2 n-halves

// ---------------- smem layout (byte offsets) ----------------
#define OFF_AHI    1024                     // W_hi slice [128 m][256 k] bf16 swizzled = 64KB
#define OFF_ALO    (OFF_AHI + 65536)        // W_lo slice                              = 64KB
#define OFF_BHI    (OFF_ALO + 65536)        // h_hi tile [32 n][256 k] bf16 swizzled   = 16KB
#define OFF_BLO    (OFF_BHI + 16384)        // h_lo tile                               = 16KB
#define OFF_WX     (OFF_BLO + 16384)        // Wx slice fp32 [128 m][130 ch]           = 66560B
#define SMEM_TOTAL (OFF_WX + 66560)

// ---------------- global scratch ----------------
__device__ unsigned g_h[2][BATCH * UNITS];   // packed (bf16 hi | bf16 lo << 16), double-buffered

// ---------------- helpers ----------------
__device__ __forceinline__ uint32_t smem_u32(const void* p) {
    uint32_t a;
    asm("{ .reg .u64 t; cvta.to.shared.u64 t, %1; cvt.u32.u64 %0, t; }" : "=r"(a) : "l"(p));
    return a;
}
#define CLUSTER_ARRIVE() asm volatile("barrier.cluster.arrive.aligned;" ::: "memory")
#define CLUSTER_WAIT()   asm volatile("barrier.cluster.wait.aligned;" ::: "memory")

// row-major tile, 512B row stride, 16B chunks XOR-swizzled by row%8 (conflict-free ldmatrix)
__device__ __forceinline__ uint32_t swz(int row, int k) {
    return (uint32_t)row * 512u
         + (((((uint32_t)k >> 3) << 4)) ^ (((uint32_t)row & 7u) << 4))
         + (((uint32_t)k & 7u) << 1);
}

__device__ __forceinline__ void ldsm_x4(uint32_t r[4], uint32_t addr) {
    asm volatile("ldmatrix.sync.aligned.m8n8.x4.shared.b16 {%0,%1,%2,%3}, [%4];"
                 : "=r"(r[0]), "=r"(r[1]), "=r"(r[2]), "=r"(r[3]) : "r"(addr));
}

__device__ __forceinline__ void mma_bf16(float c[4],
                                         uint32_t a0, uint32_t a1, uint32_t a2, uint32_t a3,
                                         uint32_t b0, uint32_t b1) {
    asm volatile("mma.sync.aligned.m16n8k16.row.col.f32.bf16.bf16.f32 "
                 "{%0,%1,%2,%3}, {%4,%5,%6,%7}, {%8,%9}, {%0,%1,%2,%3};"
                 : "+f"(c[0]), "+f"(c[1]), "+f"(c[2]), "+f"(c[3])
                 : "r"(a0), "r"(a1), "r"(a2), "r"(a3), "r"(b0), "r"(b1));
}

__device__ __forceinline__ float sigm(float x) { return 1.0f / (1.0f + __expf(-x)); }
__device__ __forceinline__ float tanh_fast(float x) { float e = __expf(2.0f * x); return 1.0f - 2.0f / (e + 1.0f); }

// ---------------- init kernel: zero g_h[0] ----------------
__global__ void init_kernel() {
    int i = blockIdx.x * blockDim.x + threadIdx.x;
    for (; i < BATCH * UNITS; i += gridDim.x * blockDim.x) g_h[0][i] = 0u;
}

// ---------------- main persistent kernel ----------------
__global__ void __launch_bounds__(NTHREADS, 1) __cluster_dims__(CPG, 1, 1)
lstm_kernel(const int* __restrict__ tokens,
            const float* __restrict__ Wx,
            const float* __restrict__ Wh,
            const float* __restrict__ bias,
            const float* __restrict__ Wd,
            const float* __restrict__ bd,
            float* __restrict__ out) {
    extern __shared__ __align__(1024) char smem[];
    const uint32_t sb = smem_u32(smem);
    const int tid = threadIdx.x;
    const int w   = tid >> 5;            // warp 0..7
    const int L   = tid & 31;
    const int mg  = w & 3;               // m-group (0..3): 32 m-rows
    const int nh  = w >> 2;              // n-half  (0..1): 16 n-cols
    const int group = blockIdx.x >> 3;
    const int r     = blockIdx.x & 7;    // cluster rank
    const int gbase = group * MBATCH;

    float* wx_s = (float*)(smem + OFF_WX);

    // ---- prologue: W_h slice (fp32 -> bf16 hi/lo), Wx fp32 slice ----
    // A-row map per 32-row m-group: gate = rw>>3 (i,j,f,o), unit_local = mg*8 + (rw&7)
    {
        const int m  = tid & 127;
        const int kh = tid >> 7;                  // k/ch half
        const int rw = m & 31;
        const int gate = rw >> 3;
        const int ulocal = (m >> 5) * 8 + (rw & 7);
        const int col = gate * 256 + r * UC + ulocal;
        for (int k = kh * 128; k < kh * 128 + 128; k++) {
            float wv = Wh[k * 1024 + col];
            __nv_bfloat16 hi = __float2bfloat16(wv);
            float rem = wv - __bfloat162float(hi);
            __nv_bfloat16 lo = __float2bfloat16(rem);
            uint32_t s = swz(m, k);
            *(__nv_bfloat16*)(smem + OFF_AHI + s) = hi;
            *(__nv_bfloat16*)(smem + OFF_ALO + s) = lo;
        }
        for (int ch = kh * 64; ch < kh * 64 + 64; ch++)
            wx_s[(gate * 32 + ulocal) * 130 + ch] = Wx[ch * 1024 + col];
    }

    // per-lane owned unit + bias regs
    const int ul = mg * 8 + (L >> 2);            // unit local 0..31
    const float bi = bias[0 * 256 + r * UC + ul];
    const float bj = bias[1 * 256 + r * UC + ul];
    const float bf = bias[2 * 256 + r * UC + ul];
    const float bo = bias[3 * 256 + r * UC + ul];
    const float* wxi = &wx_s[(0 * 32 + ul) * 130];
    const float* wxj = &wx_s[(1 * 32 + ul) * 130];
    const float* wxf = &wx_s[(2 * 32 + ul) * 130];
    const float* wxo = &wx_s[(3 * 32 + ul) * 130];

    // ---- per-lane ldmatrix addresses ----
    const int rA   = (L & 7) + 8 * ((L >> 3) & 1);
    const uint32_t koffA = (L >> 4) ? 16u : 0u;
    const int rowA0 = mg * 32 + rA;
    const int rowA1 = rowA0 + 16;
    const uint32_t xA = ((uint32_t)rowA0 & 7u) << 4;
    const uint32_t aHi0 = sb + OFF_AHI + rowA0 * 512u;
    const uint32_t aHi1 = sb + OFF_AHI + rowA1 * 512u;
    const uint32_t aLo0 = sb + OFF_ALO + rowA0 * 512u;
    const uint32_t aLo1 = sb + OFF_ALO + rowA1 * 512u;
    const int rB = L & 7;
    const uint32_t koffB = ((L >> 3) & 1) ? 16u : 0u;
    const int nB = nh * 16 + ((L >> 4) & 1) * 8 + rB;    // 16 n-rows for this n-half
    const uint32_t xB = ((uint32_t)rB & 7u) << 4;
    const uint32_t bHi = sb + OFF_BHI + nB * 512u;
    const uint32_t bLo = sb + OFF_BLO + nB * 512u;

    // per-lane batch columns: bb(e) = nh*16 + nb*8 + (L&3)*2 + j, e = nb*2+j
    int bbs[4];
#pragma unroll
    for (int nb = 0; nb < 2; nb++)
#pragma unroll
        for (int j = 0; j < 2; j++) bbs[nb * 2 + j] = nh * 16 + nb * 8 + (L & 3) * 2 + j;

    float c_reg[4];
#pragma unroll
    for (int k = 0; k < 4; k++) c_reg[k] = 0.0f;

    __syncthreads();          // wx_s / A tiles written
    CLUSTER_ARRIVE();         // phase 0 (prologue done; init_kernel zeros already visible)

    // prefetch tokens + Wx gather for t=0 (runs in barrier-skew shadow)
    float wvi[4], wvj[4], wvf[4], wvo[4];
    {
#pragma unroll
        for (int e = 0; e < 4; e++) {
            int tk = __ldg(&tokens[(gbase + bbs[e]) * SEQ + 0]);
            wvi[e] = wxi[tk]; wvj[e] = wxj[tk]; wvf[e] = wxf[tk]; wvo[e] = wxo[tk];
        }
    }

    // ---- 1024 recurrent steps ----
    for (int t = 0; t < SEQ; t++) {
        CLUSTER_WAIT();   // all CTAs' h stores for step t visible; also CTA-wide barrier

        // load h (packed bf16 hi/lo), unpack into swizzled Bhi/Blo
        {
            const uint4* src = (const uint4*)&g_h[t & 1][gbase * UNITS];
#pragma unroll
            for (int ii = 0; ii < 8; ii++) {
                int idx4 = tid + (ii << 8);
                uint4 p = __ldcg(src + idx4);
                int n  = idx4 >> 6;
                int k4 = (idx4 & 63) << 2;
                uint32_t hi01 = (p.x & 0xFFFFu) | (p.y << 16);
                uint32_t hi23 = (p.z & 0xFFFFu) | (p.w << 16);
                uint32_t lo01 = (p.x >> 16) | (p.y & 0xFFFF0000u);
                uint32_t lo23 = (p.z >> 16) | (p.w & 0xFFFF0000u);
                uint32_t s = swz(n, k4);
                *(uint2*)(smem + OFF_BHI + s) = make_uint2(hi01, hi23);
                *(uint2*)(smem + OFF_BLO + s) = make_uint2(lo01, lo23);
            }
        }
        __syncthreads();

        // ---- MMA: gates[128,32] = Whi*hhi + Whi*hlo + Wlo*hhi over K=256 ----
        float acc[2][2][4];
#pragma unroll
        for (int mt = 0; mt < 2; mt++)
#pragma unroll
            for (int nb = 0; nb < 2; nb++)
#pragma unroll
                for (int e = 0; e < 4; e++) acc[mt][nb][e] = 0.0f;

#pragma unroll 4
        for (int ks = 0; ks < 16; ks++) {
            const uint32_t ka = ((uint32_t)(ks * 32) + koffA) ^ xA;
            const uint32_t kb = ((uint32_t)(ks * 32) + koffB) ^ xB;
            uint32_t Ah0[4], Ah1[4], Al0[4], Al1[4], Bh[4], Bl[4];
            ldsm_x4(Ah0, aHi0 + ka);
            ldsm_x4(Ah1, aHi1 + ka);
            ldsm_x4(Al0, aLo0 + ka);
            ldsm_x4(Al1, aLo1 + ka);
            ldsm_x4(Bh, bHi + kb);   // regs {0,1}=n-block 0, {2,3}=n-block 1 (of this half)
            ldsm_x4(Bl, bLo + kb);
#pragma unroll
            for (int nb = 0; nb < 2; nb++) {
                mma_bf16(acc[0][nb], Ah0[0], Ah0[1], Ah0[2], Ah0[3], Bh[2 * nb], Bh[2 * nb + 1]);
                mma_bf16(acc[1][nb], Ah1[0], Ah1[1], Ah1[2], Ah1[3], Bh[2 * nb], Bh[2 * nb + 1]);
                mma_bf16(acc[0][nb], Ah0[0], Ah0[1], Ah0[2], Ah0[3], Bl[2 * nb], Bl[2 * nb + 1]);
                mma_bf16(acc[1][nb], Ah1[0], Ah1[1], Ah1[2], Ah1[3], Bl[2 * nb], Bl[2 * nb + 1]);
                mma_bf16(acc[0][nb], Al0[0], Al0[1], Al0[2], Al0[3], Bh[2 * nb], Bh[2 * nb + 1]);
                mma_bf16(acc[1][nb], Al1[0], Al1[1], Al1[2], Al1[3], Bh[2 * nb], Bh[2 * nb + 1]);
            }
        }

        // ---- LSTM elementwise in registers (lane owns unit ul, 4 batch cols) ----
        // acc[0][nb][j]=gate_i, acc[0][nb][2+j]=gate_j, acc[1][nb][j]=gate_f, acc[1][nb][2+j]=gate_o
        {
            unsigned* dst = &g_h[(t + 1) & 1][0];
#pragma unroll
            for (int nb = 0; nb < 2; nb++) {
#pragma unroll
                for (int j = 0; j < 2; j++) {
                    const int e = nb * 2 + j;
                    float gi = acc[0][nb][j]     + wvi[e] + bi;
                    float gj = acc[0][nb][2 + j] + wvj[e] + bj;
                    float gf = acc[1][nb][j]     + wvf[e] + bf;
                    float go = acc[1][nb][2 + j] + wvo[e] + bo;
                    float nc = c_reg[e] * sigm(gf + 1.0f) + sigm(gi) * tanh_fast(gj);
                    c_reg[e] = nc;
                    float nh2 = tanh_fast(nc) * sigm(go);
                    __nv_bfloat16 hi = __float2bfloat16(nh2);
                    float rem = nh2 - __bfloat162float(hi);
                    __nv_bfloat16 lo = __float2bfloat16(rem);
                    unsigned packed = (unsigned)__bfloat16_as_ushort(hi) | ((unsigned)__bfloat16_as_ushort(lo) << 16);
                    __stcg(&dst[(gbase + bbs[e]) * UNITS + r * UC + ul], packed);
                }
            }
        }
        CLUSTER_ARRIVE();   // my h(t+1) stores issued & ordered (release)

        // prefetch next step's tokens + Wx gather in the skew shadow
        {
            const int tp = (t + 1 < SEQ) ? (t + 1) : (SEQ - 1);
#pragma unroll
            for (int e = 0; e < 4; e++) {
                int tk = __ldg(&tokens[(gbase + bbs[e]) * SEQ + tp]);
                wvi[e] = wxi[tk]; wvj[e] = wxj[tk]; wvf[e] = wxf[tk]; wvo[e] = wxo[tk];
            }
        }
    }

    // ---- dense head: logits = h @ W_dense + b_dense (final h in g_h[0]) ----
    CLUSTER_WAIT();   // final h stores visible; CTA-wide barrier (safe to reuse AHI smem)
    {
        float* hs = (float*)(smem + OFF_AHI);   // reuse A region: 4 rows x 256 fp32
        const int bstart = r * 4;
        for (int i = tid; i < 4 * UNITS; i += NTHREADS) {
            unsigned p = __ldcg(&g_h[0][(gbase + bstart + (i >> 8)) * UNITS + (i & 255)]);
            hs[i] = __bfloat162float(__ushort_as_bfloat16((unsigned short)(p & 0xFFFFu))) +
                    __bfloat162float(__ushort_as_bfloat16((unsigned short)(p >> 16)));
        }
        __syncthreads();
        const int n    = tid & 127;   // output char
        const int pair = tid >> 7;    // 2 batch rows each
        float a0 = bd[n], a1 = bd[n];
        for (int k = 0; k < UNITS; k++) {
            float wv = Wd[k * NUM_CHARS + n];
            a0 += hs[(pair * 2 + 0) * 256 + k] * wv;
            a1 += hs[(pair * 2 + 1) * 256 + k] * wv;
        }
        out[(gbase + bstart + pair * 2 + 0) * NUM_CHARS + n] = a0;
        out[(gbase + bstart + pair * 2 + 1) * NUM_CHARS + n] = a1;
    }
}

// ---------------- host launcher ----------------
extern "C" void kernel_launch(void* const* d_in, const int* in_sizes, int n_in,
                              void* d_out, int out_size) {
    (void)in_sizes; (void)n_in; (void)out_size;
    const int*   tokens = (const int*)d_in[0];
    const float* Wx     = (const float*)d_in[1];
    const float* Wh     = (const float*)d_in[2];
    const float* b      = (const float*)d_in[3];
    const float* Wd     = (const float*)d_in[4];
    const float* bdn    = (const float*)d_in[5];
    float* out = (float*)d_out;

    cudaFuncSetAttribute(lstm_kernel, cudaFuncAttributeMaxDynamicSharedMemorySize, SMEM_TOTAL);

    init_kernel<<<128, 256>>>();
    lstm_kernel<<<NCTAS, NTHREADS, SMEM_TOTAL>>>(tokens, Wx, Wh, b, Wd, bdn, out);
}